// round 15
// baseline (speedup 1.0000x reference)
#include <cuda_runtime.h>
#include <cuda_fp16.h>
#include <cstdint>

// ---------------- problem constants ----------------
#define TOKENS  32
#define KDIM    8192
#define NDIM    28672
#define KSPLIT  4
#define NTILE   128
#define KTILE   128                            // one quant group per k-tile
#define TILES   (KDIM / KSPLIT / KTILE)        // 16
#define THREADS 128

// split-K fp32 scratch
__device__ float g_scratch[KSPLIT][(size_t)NDIM * TOKENS];

// ---------------- helpers ----------------
__device__ __forceinline__ uint32_t smem_u32(const void* p) {
    uint32_t a;
    asm("{ .reg .u64 t; cvta.to.shared.u64 t, %1; cvt.u32.u64 %0, t; }" : "=r"(a) : "l"(p));
    return a;
}
#define STS128(a0, r0, r1, r2, r3) \
    asm volatile("st.shared.v4.b32 [%0], {%1, %2, %3, %4};" \
        :: "r"(a0), "r"(r0), "r"(r1), "r"(r2), "r"(r3) : "memory")
#define LDMX4(r0, r1, r2, r3, addr) \
    asm volatile("ldmatrix.sync.aligned.m8n8.x4.shared.b16 {%0, %1, %2, %3}, [%4];" \
        : "=r"(r0), "=r"(r1), "=r"(r2), "=r"(r3) : "r"(addr))
#define MMA16816(c0, c1, c2, c3, a0, a1, a2, a3, b0, b1) \
    asm volatile("mma.sync.aligned.m16n8k16.row.col.f32.f16.f16.f32 " \
        "{%0,%1,%2,%3}, {%4,%5,%6,%7}, {%8,%9}, {%0,%1,%2,%3};" \
        : "+f"(c0), "+f"(c1), "+f"(c2), "+f"(c3) \
        : "r"(a0), "r"(a1), "r"(a2), "r"(a3), "r"(b0), "r"(b1))
// (w & 0x000F000F) | 0x64006400  -> half2 (1024+q_p, 1024+q_{p+4})
#define LOP3_EXT(d, a) \
    asm("lop3.b32 %0, %1, 0x000F000F, 0x64006400, 0xEA;" : "=r"(d) : "r"(a))

__device__ __forceinline__ __half2 u2h2(uint32_t v) {
    __half2 h; *reinterpret_cast<uint32_t*>(&h) = v; return h;
}
__device__ __forceinline__ uint32_t h22u(__half2 h) {
    return *reinterpret_cast<uint32_t*>(&h);
}
// pack two f32 (exactly fp16-representable here) into one half2 word
__device__ __forceinline__ uint32_t pack_h2(float a, float b) {
    return h22u(__floats2half2_rn(a, b));
}

// ---------------- main GEMM kernel (split-K) ----------------
// CTA = 128 threads = 4 warps; tile = 128 features x 128 k (one quant group).
// Per k-tile:
//   - each thread dequants one feature column (16 packed words -> 128 halfs)
//     into SMEM A, stored as the LOP3-natural (q_p, q_{p+4}) pair order,
//   - X tile loaded f32 from gmem (registers, prefetched), converted fp16 and
//     stored to SMEM in the SAME pair-permuted order -> permutation cancels
//     inside the mma dot product,
//   - both operands feed mma.m16n8k16 via ldmatrix.x4.
// SMEM rows are 256B (16 chunks of 16B) with XOR-8 chunk swizzle.
__global__ void __launch_bounds__(THREADS)
exllama_gemm_kernel(const float* __restrict__ x,
                    const uint32_t* __restrict__ qw,
                    const uint32_t* __restrict__ qz,
                    const float* __restrict__ sc)
{
    __shared__ __align__(16) uint32_t As[8192];   // 32 KB: 128 rows x 256B
    __shared__ __align__(16) uint32_t Xs[2048];   // 8 KB:  32 rows x 256B

    const int tid = threadIdx.x;
    const int w   = tid >> 5;
    const int l   = tid & 31;
    const int n0  = blockIdx.x * NTILE;
    const int ks  = blockIdx.y;

    const uint32_t abase = smem_u32(As);
    const uint32_t xbase = smem_u32(Xs);

    const int nthr = n0 + tid;           // this thread's dequant feature column
    const int xt0  = tid >> 4;           // X staging: token for i-step
    const int xc   = tid & 15;           // X staging: 16B chunk index

    float acc[2][4][4];
#pragma unroll
    for (int f = 0; f < 2; ++f)
#pragma unroll
        for (int tg = 0; tg < 4; ++tg)
#pragma unroll
            for (int i = 0; i < 4; ++i) acc[f][tg][i] = 0.f;

    uint32_t qv[16];
    float4   xa[4], xb[4];               // 8 f32 per (thread, token-step)
    float    sreg;
    uint32_t zreg;

    const int g0 = ks * TILES;

    // ---- prologue: load tile 0 operands into registers ----
    {
#pragma unroll
        for (int i = 0; i < 16; ++i)
            qv[i] = qw[(size_t)(g0 * 16 + i) * NDIM + nthr];
#pragma unroll
        for (int i = 0; i < 4; ++i) {
            const float* xp = x + (size_t)(xt0 + i * 8) * KDIM
                                + (size_t)g0 * KTILE + xc * 8;
            xa[i] = *reinterpret_cast<const float4*>(xp);
            xb[i] = *reinterpret_cast<const float4*>(xp + 4);
        }
        sreg = sc[(size_t)g0 * NDIM + nthr];
        zreg = (qz[(size_t)g0 * (NDIM / 8) + (nthr >> 3)] >> ((nthr & 7) * 4)) & 15u;
    }

#pragma unroll 1
    for (int it = 0; it < TILES; ++it) {
        // ---- stage A: dequant 16 words, LOP3-natural pair order ----
        {
            const __half2 s2  = __half2half2(__float2half(sreg));   // exact
            const __half2 zc2 = __half2half2(
                __ushort_as_half((unsigned short)(0x6400u + zreg + 1u)));
            const uint32_t arow = abase + (uint32_t)tid * 256u;
#pragma unroll
            for (int i = 0; i < 16; ++i) {
                const uint32_t wv = qv[i];
                uint32_t p0, p1, p2, p3;
                LOP3_EXT(p0, wv);          // (1024+q0, 1024+q4)
                LOP3_EXT(p1, wv >> 4);     // (1024+q1, 1024+q5)
                LOP3_EXT(p2, wv >> 8);     // (1024+q2, 1024+q6)
                LOP3_EXT(p3, wv >> 12);    // (1024+q3, 1024+q7)
                // exact: (1024+q) - (1024+z+1) = q-z-1, then * s (ref rounding)
                const uint32_t r0 = h22u(__hmul2(__hsub2(u2h2(p0), zc2), s2)); // (w0,w4)
                const uint32_t r1 = h22u(__hmul2(__hsub2(u2h2(p1), zc2), s2)); // (w1,w5)
                const uint32_t r2 = h22u(__hmul2(__hsub2(u2h2(p2), zc2), s2)); // (w2,w6)
                const uint32_t r3 = h22u(__hmul2(__hsub2(u2h2(p3), zc2), s2)); // (w3,w7)
                STS128(arow + (uint32_t)(((i ^ (tid & 7)) << 4)), r0, r1, r2, r3);
            }
        }
        // ---- stage X: f32 -> fp16, SAME pair-permuted order ----
#pragma unroll
        for (int i = 0; i < 4; ++i) {
            const int t = xt0 + i * 8;
            const uint32_t r0 = pack_h2(xa[i].x, xb[i].x);   // (x0, x4)
            const uint32_t r1 = pack_h2(xa[i].y, xb[i].y);   // (x1, x5)
            const uint32_t r2 = pack_h2(xa[i].z, xb[i].z);   // (x2, x6)
            const uint32_t r3 = pack_h2(xa[i].w, xb[i].w);   // (x3, x7)
            STS128(xbase + (uint32_t)t * 256u + (uint32_t)(((xc ^ (t & 7)) << 4)),
                   r0, r1, r2, r3);
        }
        __syncthreads();

        // ---- prefetch tile it+1 into registers (overlaps compute below) ----
        if (it + 1 < TILES) {
            const int g = g0 + it + 1;
#pragma unroll
            for (int i = 0; i < 16; ++i)
                qv[i] = qw[(size_t)(g * 16 + i) * NDIM + nthr];
#pragma unroll
            for (int i = 0; i < 4; ++i) {
                const float* xp = x + (size_t)(xt0 + i * 8) * KDIM
                                    + (size_t)g * KTILE + xc * 8;
                xa[i] = *reinterpret_cast<const float4*>(xp);
                xb[i] = *reinterpret_cast<const float4*>(xp + 4);
            }
            sreg = sc[(size_t)g * NDIM + nthr];
            zreg = (qz[(size_t)g * (NDIM / 8) + (nthr >> 3)] >> ((nthr & 7) * 4)) & 15u;
        }

        // ---- compute: 8 k16 blocks, fragments via ldmatrix ----
        const int t_a = (l & 7) + ((l >> 4) & 1) * 8;  // B ldmatrix token row
        const int fr0 = w * 32 + (l & 15);             // A ldmatrix feature row
#pragma unroll
        for (int j = 0; j < 8; ++j) {
            uint32_t b[8];
            const int cc = 2 * j + ((l >> 3) & 1);
            const uint32_t ba = xbase + (uint32_t)t_a * 256u
                              + (uint32_t)(((cc ^ (t_a & 7)) << 4));
            LDMX4(b[0], b[1], b[2], b[3], ba);             // tokens 0-15
            LDMX4(b[4], b[5], b[6], b[7], ba + 16 * 256);  // tokens 16-31

            const int oct = 2 * j + (l >> 4);              // A k-octet
#pragma unroll
            for (int f = 0; f < 2; ++f) {
                const int row = fr0 + f * 16;
                uint32_t a0, a1, a2, a3;
                LDMX4(a0, a1, a2, a3,
                      abase + (uint32_t)row * 256u
                            + (uint32_t)(((oct ^ (row & 7)) << 4)));
#pragma unroll
                for (int tg = 0; tg < 4; ++tg)
                    MMA16816(acc[f][tg][0], acc[f][tg][1], acc[f][tg][2], acc[f][tg][3],
                             a0, a1, a2, a3, b[2 * tg], b[2 * tg + 1]);
            }
        }
        __syncthreads();
    }

    // ---- write fp32 partials: scratch[ks][n * TOKENS + t] ----
#pragma unroll
    for (int f = 0; f < 2; ++f) {
        const int nb = n0 + w * 32 + f * 16 + (l >> 2);
#pragma unroll
        for (int tg = 0; tg < 4; ++tg) {
            const int tok = tg * 8 + (l & 3) * 2;
            *reinterpret_cast<float2*>(&g_scratch[ks][(size_t)nb * TOKENS + tok]) =
                make_float2(acc[f][tg][0], acc[f][tg][1]);
            *reinterpret_cast<float2*>(&g_scratch[ks][(size_t)(nb + 8) * TOKENS + tok]) =
                make_float2(acc[f][tg][2], acc[f][tg][3]);
        }
    }
}

// ---------------- split-sum + bias + transpose epilogue (f32 out) ----------------
__global__ void __launch_bounds__(256)
reduce_bias_kernel(const float* __restrict__ bias, float* __restrict__ out)
{
    __shared__ float s[64 * 33];
    const int n0  = blockIdx.x * 64;
    const int tid = threadIdx.x;
#pragma unroll
    for (int i = 0; i < 8; ++i) {
        const int v  = tid + i * 256;
        const int nl = v >> 5, t = v & 31;
        const size_t idx = (size_t)(n0 + nl) * TOKENS + t;
        s[nl * 33 + t] = g_scratch[0][idx] + g_scratch[1][idx]
                       + g_scratch[2][idx] + g_scratch[3][idx];
    }
    __syncthreads();
#pragma unroll
    for (int i = 0; i < 8; ++i) {
        const int v  = tid + i * 256;
        const int t = v >> 6, nl = v & 63;
        // ref-matched rounding: h16(acc) + h16(bias) in fp16, then widen
        const __half h = __hadd(__float2half(s[nl * 33 + t]),
                                __float2half(bias[n0 + nl]));
        out[(size_t)t * NDIM + n0 + nl] = __half2float(h);
    }
}

// ---------------- launch ----------------
// Bind inputs by element count (all five unique); fall back to positional.
//   x: 262144  qweight: 29360128  qzeros: 229376  scales: 1835008  bias: 28672
extern "C" void kernel_launch(void* const* d_in, const int* in_sizes, int n_in,
                              void* d_out, int out_size)
{
    const float*    x    = nullptr;
    const uint32_t* qw   = nullptr;
    const uint32_t* qz   = nullptr;
    const float*    sc   = nullptr;
    const float*    bias = nullptr;

    for (int i = 0; i < n_in; ++i) {
        switch (in_sizes[i]) {
            case 262144:   x    = (const float*)   d_in[i]; break;
            case 29360128: qw   = (const uint32_t*)d_in[i]; break;
            case 229376:   qz   = (const uint32_t*)d_in[i]; break;
            case 1835008:  sc   = (const float*)   d_in[i]; break;
            case 28672:    bias = (const float*)   d_in[i]; break;
            default: break;
        }
    }
    if (!x || !qw || !qz || !sc || !bias) {   // positional fallback
        x    = (const float*)   d_in[0];
        qw   = (const uint32_t*)d_in[1];
        qz   = (const uint32_t*)d_in[2];
        sc   = (const float*)   d_in[3];
        bias = (const float*)   d_in[4];
    }
    float* out = (float*)d_out;

    dim3 grid(NDIM / NTILE, KSPLIT);
    exllama_gemm_kernel<<<grid, THREADS>>>(x, qw, qz, sc);
    reduce_bias_kernel<<<NDIM / 64, 256>>>(bias, out);
}

// round 16
// speedup vs baseline: 1.0298x; 1.0298x over previous
#include <cuda_runtime.h>
#include <cuda_fp16.h>
#include <cstdint>

// ---------------- problem constants ----------------
#define TOKENS  32
#define KDIM    8192
#define NDIM    28672
#define KSPLIT  4
#define NTILE   128
#define KTILE   128                            // one quant group per k-tile
#define TILES   (KDIM / KSPLIT / KTILE)        // 16
#define THREADS 128

// fp16 PERMUTED copy of x (pairs (x0,x4)(x1,x5)(x2,x6)(x3,x7) per 8-group)
__device__ __half g_xh[(size_t)TOKENS * KDIM];
// split-K fp32 scratch
__device__ float  g_scratch[KSPLIT][(size_t)NDIM * TOKENS];

// ---------------- helpers ----------------
__device__ __forceinline__ uint32_t smem_u32(const void* p) {
    uint32_t a;
    asm("{ .reg .u64 t; cvta.to.shared.u64 t, %1; cvt.u32.u64 %0, t; }" : "=r"(a) : "l"(p));
    return a;
}
#define STS128(a0, r0, r1, r2, r3) \
    asm volatile("st.shared.v4.b32 [%0], {%1, %2, %3, %4};" \
        :: "r"(a0), "r"(r0), "r"(r1), "r"(r2), "r"(r3) : "memory")
#define LDMX4(r0, r1, r2, r3, addr) \
    asm volatile("ldmatrix.sync.aligned.m8n8.x4.shared.b16 {%0, %1, %2, %3}, [%4];" \
        : "=r"(r0), "=r"(r1), "=r"(r2), "=r"(r3) : "r"(addr))
#define MMA16816(c0, c1, c2, c3, a0, a1, a2, a3, b0, b1) \
    asm volatile("mma.sync.aligned.m16n8k16.row.col.f32.f16.f16.f32 " \
        "{%0,%1,%2,%3}, {%4,%5,%6,%7}, {%8,%9}, {%0,%1,%2,%3};" \
        : "+f"(c0), "+f"(c1), "+f"(c2), "+f"(c3) \
        : "r"(a0), "r"(a1), "r"(a2), "r"(a3), "r"(b0), "r"(b1))
// (w & 0x000F000F) | 0x64006400  -> half2 (1024+q_p, 1024+q_{p+4})
#define LOP3_EXT(d, a) \
    asm("lop3.b32 %0, %1, 0x000F000F, 0x64006400, 0xEA;" : "=r"(d) : "r"(a))
// 16B gmem -> smem async copy
#define CP_ASYNC16(dst, src) \
    asm volatile("cp.async.ca.shared.global [%0], [%1], 16;" \
        :: "r"(dst), "l"(src) : "memory")
#define CP_ASYNC_COMMIT() asm volatile("cp.async.commit_group;" ::: "memory")
#define CP_ASYNC_WAIT0()  asm volatile("cp.async.wait_group 0;" ::: "memory")

__device__ __forceinline__ __half2 u2h2(uint32_t v) {
    __half2 h; *reinterpret_cast<uint32_t*>(&h) = v; return h;
}
__device__ __forceinline__ uint32_t h22u(__half2 h) {
    return *reinterpret_cast<uint32_t*>(&h);
}

// ---------------- x convert kernel: f32 -> fp16, PAIR-PERMUTED ----------------
__global__ void __launch_bounds__(256)
xconvert_kernel(const float* __restrict__ x)
{
    const int i = (blockIdx.x * 256 + threadIdx.x) * 8;
    const float4 a = *reinterpret_cast<const float4*>(x + i);
    const float4 b = *reinterpret_cast<const float4*>(x + i + 4);
    uint4 r;
    r.x = h22u(__floats2half2_rn(a.x, b.x));   // (x0, x4)
    r.y = h22u(__floats2half2_rn(a.y, b.y));   // (x1, x5)
    r.z = h22u(__floats2half2_rn(a.z, b.z));   // (x2, x6)
    r.w = h22u(__floats2half2_rn(a.w, b.w));   // (x3, x7)
    *reinterpret_cast<uint4*>(&g_xh[i]) = r;
}

// ---------------- main GEMM kernel (split-K, 4 CTAs/SM) ----------------
// CTA = 128 threads = 4 warps; tile = 128 features x 128 k (one quant group).
// Dequant to SMEM A in LOP3-natural (q_p, q_{p+4}) pair order; X pre-permuted
// identically in g_xh, staged via cp.async into double-buffered SMEM; both
// operands feed mma.m16n8k16 via ldmatrix.x4. XOR-8 16B-chunk swizzle.
// __launch_bounds__(128, 4): <=128 regs so 4 CTAs (16 warps) fit per SM.
__global__ void __launch_bounds__(THREADS, 4)
exllama_gemm_kernel(const uint32_t* __restrict__ qw,
                    const uint32_t* __restrict__ qz,
                    const float* __restrict__ sc)
{
    __shared__ __align__(16) uint32_t As[8192];      // 32 KB A tile
    __shared__ __align__(16) uint32_t Xs[2][2048];   // 2 x 8KB X tiles

    const int tid = threadIdx.x;
    const int w   = tid >> 5;
    const int l   = tid & 31;
    const int n0  = blockIdx.x * NTILE;
    const int ks  = blockIdx.y;

    const uint32_t abase = smem_u32(As);
    const uint32_t xs0   = smem_u32(&Xs[0][0]);

    const int nthr = n0 + tid;           // this thread's dequant feature column
    const int xt0  = tid >> 4;           // X staging: token for i-step
    const int xc   = tid & 15;           // X staging: 16B chunk index

    float acc[2][4][4];
#pragma unroll
    for (int f = 0; f < 2; ++f)
#pragma unroll
        for (int tg = 0; tg < 4; ++tg)
#pragma unroll
            for (int i = 0; i < 4; ++i) acc[f][tg][i] = 0.f;

    uint32_t qv[16];
    float    sreg;
    uint32_t zreg;

    const int g0 = ks * TILES;

    auto load_q = [&](int g) {
#pragma unroll
        for (int i = 0; i < 16; ++i)
            qv[i] = qw[(size_t)(g * 16 + i) * NDIM + nthr];
        sreg = sc[(size_t)g * NDIM + nthr];
        zreg = (qz[(size_t)g * (NDIM / 8) + (nthr >> 3)] >> ((nthr & 7) * 4)) & 15u;
    };
    auto cp_x = [&](int g, int buf) {
        const uint32_t xb = xs0 + (uint32_t)buf * 8192u;
#pragma unroll
        for (int i = 0; i < 4; ++i) {
            const int t = xt0 + i * 8;
            CP_ASYNC16(xb + (uint32_t)t * 256u + (uint32_t)(((xc ^ (t & 7)) << 4)),
                       &g_xh[(size_t)t * KDIM + (size_t)g * KTILE + xc * 8]);
        }
        CP_ASYNC_COMMIT();
    };

    // ---- prologue: qweight(tile0) in regs, X(tile0) in flight ----
    load_q(g0);
    cp_x(g0, 0);

#pragma unroll 1
    for (int it = 0; it < TILES; ++it) {
        // ---- stage A: dequant 16 words, LOP3-natural pair order ----
        {
            const __half2 s2  = __half2half2(__float2half(sreg));   // exact
            const __half2 zc2 = __half2half2(
                __ushort_as_half((unsigned short)(0x6400u + zreg + 1u)));
            const uint32_t arow = abase + (uint32_t)tid * 256u;
#pragma unroll
            for (int i = 0; i < 16; ++i) {
                const uint32_t wv = qv[i];
                uint32_t p0, p1, p2, p3;
                LOP3_EXT(p0, wv);          // (1024+q0, 1024+q4)
                LOP3_EXT(p1, wv >> 4);     // (1024+q1, 1024+q5)
                LOP3_EXT(p2, wv >> 8);     // (1024+q2, 1024+q6)
                LOP3_EXT(p3, wv >> 12);    // (1024+q3, 1024+q7)
                // exact: (1024+q) - (1024+z+1) = q-z-1, then * s (ref rounding)
                const uint32_t r0 = h22u(__hmul2(__hsub2(u2h2(p0), zc2), s2));
                const uint32_t r1 = h22u(__hmul2(__hsub2(u2h2(p1), zc2), s2));
                const uint32_t r2 = h22u(__hmul2(__hsub2(u2h2(p2), zc2), s2));
                const uint32_t r3 = h22u(__hmul2(__hsub2(u2h2(p3), zc2), s2));
                STS128(arow + (uint32_t)(((i ^ (tid & 7)) << 4)), r0, r1, r2, r3);
            }
        }
        CP_ASYNC_WAIT0();
        __syncthreads();                 // A(it), X(it) ready; X buf (it+1)&1 free
        if (it + 1 < TILES) cp_x(g0 + it + 1, (it + 1) & 1);

        // ---- prefetch qweight/meta for tile it+1 (overlaps compute) ----
        if (it + 1 < TILES) load_q(g0 + it + 1);

        // ---- compute: 8 k16 blocks, fragments via ldmatrix ----
        const uint32_t xb  = xs0 + (uint32_t)(it & 1) * 8192u;
        const int t_a = (l & 7) + ((l >> 4) & 1) * 8;  // B ldmatrix token row
        const int fr0 = w * 32 + (l & 15);             // A ldmatrix feature row
#pragma unroll
        for (int j = 0; j < 8; ++j) {
            uint32_t b[8];
            const int cc = 2 * j + ((l >> 3) & 1);
            const uint32_t ba = xb + (uint32_t)t_a * 256u
                              + (uint32_t)(((cc ^ (t_a & 7)) << 4));
            LDMX4(b[0], b[1], b[2], b[3], ba);             // tokens 0-15
            LDMX4(b[4], b[5], b[6], b[7], ba + 16 * 256);  // tokens 16-31

            const int oct = 2 * j + (l >> 4);              // A k-octet
#pragma unroll
            for (int f = 0; f < 2; ++f) {
                const int row = fr0 + f * 16;
                uint32_t a0, a1, a2, a3;
                LDMX4(a0, a1, a2, a3,
                      abase + (uint32_t)row * 256u
                            + (uint32_t)(((oct ^ (row & 7)) << 4)));
#pragma unroll
                for (int tg = 0; tg < 4; ++tg)
                    MMA16816(acc[f][tg][0], acc[f][tg][1], acc[f][tg][2], acc[f][tg][3],
                             a0, a1, a2, a3, b[2 * tg], b[2 * tg + 1]);
            }
        }
        __syncthreads();                 // A consumed -> safe to re-stage
    }

    // ---- write fp32 partials: scratch[ks][n * TOKENS + t] ----
#pragma unroll
    for (int f = 0; f < 2; ++f) {
        const int nb = n0 + w * 32 + f * 16 + (l >> 2);
#pragma unroll
        for (int tg = 0; tg < 4; ++tg) {
            const int tok = tg * 8 + (l & 3) * 2;
            *reinterpret_cast<float2*>(&g_scratch[ks][(size_t)nb * TOKENS + tok]) =
                make_float2(acc[f][tg][0], acc[f][tg][1]);
            *reinterpret_cast<float2*>(&g_scratch[ks][(size_t)(nb + 8) * TOKENS + tok]) =
                make_float2(acc[f][tg][2], acc[f][tg][3]);
        }
    }
}

// ---------------- split-sum + bias + transpose epilogue (f32 out) ----------------
// 896 blocks x (32 n x 32 t): more parallelism to hide memory latency.
__global__ void __launch_bounds__(256)
reduce_bias_kernel(const float* __restrict__ bias, float* __restrict__ out)
{
    __shared__ float s[32 * 33];
    const int n0  = blockIdx.x * 32;
    const int tid = threadIdx.x;
#pragma unroll
    for (int i = 0; i < 4; ++i) {
        const int v  = tid + i * 256;
        const int nl = v >> 5, t = v & 31;
        const size_t idx = (size_t)(n0 + nl) * TOKENS + t;
        s[nl * 33 + t] = g_scratch[0][idx] + g_scratch[1][idx]
                       + g_scratch[2][idx] + g_scratch[3][idx];
    }
    __syncthreads();
#pragma unroll
    for (int i = 0; i < 4; ++i) {
        const int v  = tid + i * 256;
        const int t = v >> 5, nl = v & 31;
        // ref-matched rounding: h16(acc) + h16(bias) in fp16, then widen
        const __half h = __hadd(__float2half(s[nl * 33 + t]),
                                __float2half(bias[n0 + nl]));
        out[(size_t)t * NDIM + n0 + nl] = __half2float(h);
    }
}

// ---------------- launch ----------------
// Bind inputs by element count (all five unique); fall back to positional.
//   x: 262144  qweight: 29360128  qzeros: 229376  scales: 1835008  bias: 28672
extern "C" void kernel_launch(void* const* d_in, const int* in_sizes, int n_in,
                              void* d_out, int out_size)
{
    const float*    x    = nullptr;
    const uint32_t* qw   = nullptr;
    const uint32_t* qz   = nullptr;
    const float*    sc   = nullptr;
    const float*    bias = nullptr;

    for (int i = 0; i < n_in; ++i) {
        switch (in_sizes[i]) {
            case 262144:   x    = (const float*)   d_in[i]; break;
            case 29360128: qw   = (const uint32_t*)d_in[i]; break;
            case 229376:   qz   = (const uint32_t*)d_in[i]; break;
            case 1835008:  sc   = (const float*)   d_in[i]; break;
            case 28672:    bias = (const float*)   d_in[i]; break;
            default: break;
        }
    }
    if (!x || !qw || !qz || !sc || !bias) {   // positional fallback
        x    = (const float*)   d_in[0];
        qw   = (const uint32_t*)d_in[1];
        qz   = (const uint32_t*)d_in[2];
        sc   = (const float*)   d_in[3];
        bias = (const float*)   d_in[4];
    }
    float* out = (float*)d_out;

    xconvert_kernel<<<TOKENS * KDIM / (256 * 8), 256>>>(x);
    dim3 grid(NDIM / NTILE, KSPLIT);
    exllama_gemm_kernel<<<grid, THREADS>>>(qw, qz, sc);
    reduce_bias_kernel<<<NDIM / 32, 256>>>(bias, out);
}

// round 17
// speedup vs baseline: 1.1277x; 1.0951x over previous
#include <cuda_runtime.h>
#include <cuda_fp16.h>
#include <cstdint>

// ---------------- problem constants ----------------
#define TOKENS  32
#define KDIM    8192
#define NDIM    28672
#define KSPLIT  2
#define NTILE   128
#define KTILE   128                            // one quant group per k-tile
#define TILES   (KDIM / KSPLIT / KTILE)        // 32
#define THREADS 128

// fp16 PERMUTED copy of x (pairs (x0,x4)(x1,x5)(x2,x6)(x3,x7) per 8-group)
__device__ __half g_xh[(size_t)TOKENS * KDIM];
// split-K fp32 scratch
__device__ float  g_scratch[KSPLIT][(size_t)NDIM * TOKENS];

// ---------------- helpers ----------------
__device__ __forceinline__ uint32_t smem_u32(const void* p) {
    uint32_t a;
    asm("{ .reg .u64 t; cvta.to.shared.u64 t, %1; cvt.u32.u64 %0, t; }" : "=r"(a) : "l"(p));
    return a;
}
#define STS128(a0, r0, r1, r2, r3) \
    asm volatile("st.shared.v4.b32 [%0], {%1, %2, %3, %4};" \
        :: "r"(a0), "r"(r0), "r"(r1), "r"(r2), "r"(r3) : "memory")
#define LDMX4(r0, r1, r2, r3, addr) \
    asm volatile("ldmatrix.sync.aligned.m8n8.x4.shared.b16 {%0, %1, %2, %3}, [%4];" \
        : "=r"(r0), "=r"(r1), "=r"(r2), "=r"(r3) : "r"(addr))
#define MMA16816(c0, c1, c2, c3, a0, a1, a2, a3, b0, b1) \
    asm volatile("mma.sync.aligned.m16n8k16.row.col.f32.f16.f16.f32 " \
        "{%0,%1,%2,%3}, {%4,%5,%6,%7}, {%8,%9}, {%0,%1,%2,%3};" \
        : "+f"(c0), "+f"(c1), "+f"(c2), "+f"(c3) \
        : "r"(a0), "r"(a1), "r"(a2), "r"(a3), "r"(b0), "r"(b1))
// (w & 0x000F000F) | 0x64006400  -> half2 (1024+q_p, 1024+q_{p+4})
#define LOP3_EXT(d, a) \
    asm("lop3.b32 %0, %1, 0x000F000F, 0x64006400, 0xEA;" : "=r"(d) : "r"(a))
// 16B gmem -> smem async copy
#define CP_ASYNC16(dst, src) \
    asm volatile("cp.async.ca.shared.global [%0], [%1], 16;" \
        :: "r"(dst), "l"(src) : "memory")
#define CP_ASYNC_WAIT_ALL() \
    asm volatile("cp.async.commit_group;\n\tcp.async.wait_group 0;" ::: "memory")

__device__ __forceinline__ __half2 u2h2(uint32_t v) {
    __half2 h; *reinterpret_cast<uint32_t*>(&h) = v; return h;
}
__device__ __forceinline__ uint32_t h22u(__half2 h) {
    return *reinterpret_cast<uint32_t*>(&h);
}

// ---------------- x convert kernel: f32 -> fp16, PAIR-PERMUTED ----------------
// For each 8-element k-group: store (x0,x4),(x1,x5),(x2,x6),(x3,x7) — the
// exact half order the A-dequant LOP3 produces, so the GEMM needs no PRMT.
__global__ void __launch_bounds__(256)
xconvert_kernel(const float* __restrict__ x)
{
    const int i = (blockIdx.x * 256 + threadIdx.x) * 8;
    const float4 a = *reinterpret_cast<const float4*>(x + i);
    const float4 b = *reinterpret_cast<const float4*>(x + i + 4);
    uint4 r;
    r.x = h22u(__floats2half2_rn(a.x, b.x));   // (x0, x4)
    r.y = h22u(__floats2half2_rn(a.y, b.y));   // (x1, x5)
    r.z = h22u(__floats2half2_rn(a.z, b.z));   // (x2, x6)
    r.w = h22u(__floats2half2_rn(a.w, b.w));   // (x3, x7)
    *reinterpret_cast<uint4*>(&g_xh[i]) = r;
}

// ---------------- main GEMM kernel (split-K, single-wave residency) ----------------
// Identical to the 72.2us R10 kernel except __launch_bounds__(128, 4):
// <=128 regs -> 4-CTA/SM capacity (592 slots) -> all 448 CTAs resident in ONE
// wave, eliminating the 4-CTA straggler wave that serialized a full CTA-time.
__global__ void __launch_bounds__(THREADS, 4)
exllama_gemm_kernel(const uint32_t* __restrict__ qw,
                    const uint32_t* __restrict__ qz,
                    const float* __restrict__ sc)
{
    __shared__ __align__(16) uint32_t As[8192];   // 32 KB: 128 rows x 256B
    __shared__ __align__(16) uint32_t Xs[2048];   // 8 KB:  32 rows x 256B

    const int tid = threadIdx.x;
    const int w   = tid >> 5;
    const int l   = tid & 31;
    const int n0  = blockIdx.x * NTILE;
    const int ks  = blockIdx.y;

    const uint32_t abase = smem_u32(As);
    const uint32_t xbase = smem_u32(Xs);

    const int nthr = n0 + tid;           // this thread's dequant feature column
    const int xt0  = tid >> 4;           // X staging: token for i-step
    const int xc   = tid & 15;           // X staging: 16B chunk index

    float acc[2][4][4];
#pragma unroll
    for (int f = 0; f < 2; ++f)
#pragma unroll
        for (int tg = 0; tg < 4; ++tg)
#pragma unroll
            for (int i = 0; i < 4; ++i) acc[f][tg][i] = 0.f;

    uint32_t qv[16];
    float    sreg;
    uint32_t zreg;

    // ---- prologue: tile 0 qweight/meta into registers; X via cp.async ----
    {
        const int g = ks * TILES;
#pragma unroll
        for (int i = 0; i < 16; ++i)
            qv[i] = qw[(size_t)(g * 16 + i) * NDIM + nthr];
        sreg = sc[(size_t)g * NDIM + nthr];
        zreg = (qz[(size_t)g * (NDIM / 8) + (nthr >> 3)] >> ((nthr & 7) * 4)) & 15u;
#pragma unroll
        for (int i = 0; i < 4; ++i) {
            const int t = xt0 + i * 8;
            CP_ASYNC16(xbase + (uint32_t)t * 256u + (uint32_t)(((xc ^ (t & 7)) << 4)),
                       &g_xh[(size_t)t * KDIM + (size_t)g * KTILE + xc * 8]);
        }
    }

#pragma unroll 1
    for (int it = 0; it < TILES; ++it) {
        const int g = ks * TILES + it;

        // ---- stage A: dequant 16 words, LOP3-natural pair order ----
        {
            const __half2 s2  = __half2half2(__float2half(sreg));   // exact
            const __half2 zc2 = __half2half2(
                __ushort_as_half((unsigned short)(0x6400u + zreg + 1u)));
            const uint32_t arow = abase + (uint32_t)tid * 256u;
#pragma unroll
            for (int i = 0; i < 16; ++i) {
                const uint32_t wv = qv[i];
                uint32_t p0, p1, p2, p3;
                LOP3_EXT(p0, wv);          // (1024+q0, 1024+q4)
                LOP3_EXT(p1, wv >> 4);     // (1024+q1, 1024+q5)
                LOP3_EXT(p2, wv >> 8);     // (1024+q2, 1024+q6)
                LOP3_EXT(p3, wv >> 12);    // (1024+q3, 1024+q7)
                // exact: (1024+q) - (1024+z+1) = q-z-1, then * s (ref rounding)
                const uint32_t r0 = h22u(__hmul2(__hsub2(u2h2(p0), zc2), s2));
                const uint32_t r1 = h22u(__hmul2(__hsub2(u2h2(p1), zc2), s2));
                const uint32_t r2 = h22u(__hmul2(__hsub2(u2h2(p2), zc2), s2));
                const uint32_t r3 = h22u(__hmul2(__hsub2(u2h2(p3), zc2), s2));
                STS128(arow + (uint32_t)(((i ^ (tid & 7)) << 4)), r0, r1, r2, r3);
            }
        }
        CP_ASYNC_WAIT_ALL();
        __syncthreads();                 // A(it), X(it) ready

        // ---- prefetch qweight/meta for tile it+1 (overlaps compute) ----
        const int gn = g + 1;
        if (it + 1 < TILES) {
#pragma unroll
            for (int i = 0; i < 16; ++i)
                qv[i] = qw[(size_t)(gn * 16 + i) * NDIM + nthr];
            sreg = sc[(size_t)gn * NDIM + nthr];
            zreg = (qz[(size_t)gn * (NDIM / 8) + (nthr >> 3)] >> ((nthr & 7) * 4)) & 15u;
        }

        // ---- compute: 8 k16 blocks, fragments via ldmatrix ----
        const int t_a = (l & 7) + ((l >> 4) & 1) * 8;  // B ldmatrix token row
        const int fr0 = w * 32 + (l & 15);             // A ldmatrix feature row
#pragma unroll
        for (int j = 0; j < 8; ++j) {
            uint32_t b[8];
            const int cc = 2 * j + ((l >> 3) & 1);
            const uint32_t ba = xbase + (uint32_t)t_a * 256u
                              + (uint32_t)(((cc ^ (t_a & 7)) << 4));
            LDMX4(b[0], b[1], b[2], b[3], ba);             // tokens 0-15
            LDMX4(b[4], b[5], b[6], b[7], ba + 16 * 256);  // tokens 16-31

            const int oct = 2 * j + (l >> 4);              // A k-octet
#pragma unroll
            for (int f = 0; f < 2; ++f) {
                const int row = fr0 + f * 16;
                uint32_t a0, a1, a2, a3;
                LDMX4(a0, a1, a2, a3,
                      abase + (uint32_t)row * 256u
                            + (uint32_t)(((oct ^ (row & 7)) << 4)));
#pragma unroll
                for (int tg = 0; tg < 4; ++tg)
                    MMA16816(acc[f][tg][0], acc[f][tg][1], acc[f][tg][2], acc[f][tg][3],
                             a0, a1, a2, a3, b[2 * tg], b[2 * tg + 1]);
            }
        }
        __syncthreads();                 // X consumed -> buffer free

        // ---- issue X cp.async for tile it+1 ----
        if (it + 1 < TILES) {
#pragma unroll
            for (int i = 0; i < 4; ++i) {
                const int t = xt0 + i * 8;
                CP_ASYNC16(xbase + (uint32_t)t * 256u
                               + (uint32_t)(((xc ^ (t & 7)) << 4)),
                           &g_xh[(size_t)t * KDIM + (size_t)gn * KTILE + xc * 8]);
            }
        }
    }

    // ---- write fp32 partials: scratch[ks][n * TOKENS + t] ----
#pragma unroll
    for (int f = 0; f < 2; ++f) {
        const int nb = n0 + w * 32 + f * 16 + (l >> 2);
#pragma unroll
        for (int tg = 0; tg < 4; ++tg) {
            const int tok = tg * 8 + (l & 3) * 2;
            *reinterpret_cast<float2*>(&g_scratch[ks][(size_t)nb * TOKENS + tok]) =
                make_float2(acc[f][tg][0], acc[f][tg][1]);
            *reinterpret_cast<float2*>(&g_scratch[ks][(size_t)(nb + 8) * TOKENS + tok]) =
                make_float2(acc[f][tg][2], acc[f][tg][3]);
        }
    }
}

// ---------------- split-sum + bias + transpose epilogue (f32 out) ----------------
__global__ void __launch_bounds__(256)
reduce_bias_kernel(const float* __restrict__ bias, float* __restrict__ out)
{
    __shared__ float s[64 * 33];
    const int n0  = blockIdx.x * 64;
    const int tid = threadIdx.x;
#pragma unroll
    for (int i = 0; i < 8; ++i) {
        const int v  = tid + i * 256;
        const int nl = v >> 5, t = v & 31;
        const size_t idx = (size_t)(n0 + nl) * TOKENS + t;
        s[nl * 33 + t] = g_scratch[0][idx] + g_scratch[1][idx];
    }
    __syncthreads();
#pragma unroll
    for (int i = 0; i < 8; ++i) {
        const int v  = tid + i * 256;
        const int t = v >> 6, nl = v & 63;
        // ref-matched rounding: h16(acc) + h16(bias) in fp16, then widen
        const __half h = __hadd(__float2half(s[nl * 33 + t]),
                                __float2half(bias[n0 + nl]));
        out[(size_t)t * NDIM + n0 + nl] = __half2float(h);
    }
}

// ---------------- launch ----------------
// Bind inputs by element count (all five unique); fall back to positional.
//   x: 262144  qweight: 29360128  qzeros: 229376  scales: 1835008  bias: 28672
extern "C" void kernel_launch(void* const* d_in, const int* in_sizes, int n_in,
                              void* d_out, int out_size)
{
    const float*    x    = nullptr;
    const uint32_t* qw   = nullptr;
    const uint32_t* qz   = nullptr;
    const float*    sc   = nullptr;
    const float*    bias = nullptr;

    for (int i = 0; i < n_in; ++i) {
        switch (in_sizes[i]) {
            case 262144:   x    = (const float*)   d_in[i]; break;
            case 29360128: qw   = (const uint32_t*)d_in[i]; break;
            case 229376:   qz   = (const uint32_t*)d_in[i]; break;
            case 1835008:  sc   = (const float*)   d_in[i]; break;
            case 28672:    bias = (const float*)   d_in[i]; break;
            default: break;
        }
    }
    if (!x || !qw || !qz || !sc || !bias) {   // positional fallback
        x    = (const float*)   d_in[0];
        qw   = (const uint32_t*)d_in[1];
        qz   = (const uint32_t*)d_in[2];
        sc   = (const float*)   d_in[3];
        bias = (const float*)   d_in[4];
    }
    float* out = (float*)d_out;

    xconvert_kernel<<<TOKENS * KDIM / (256 * 8), 256>>>(x);
    dim3 grid(NDIM / NTILE, KSPLIT);
    exllama_gemm_kernel<<<grid, THREADS>>>(qw, qz, sc);
    reduce_bias_kernel<<<NDIM / 64, 256>>>(bias, out);
}